// round 15
// baseline (speedup 1.0000x reference)
#include <cuda_runtime.h>
#include <cstdint>
#include <math.h>

#define CH 512
#define NG 64
#define N_SAMP 16
#define H 64
#define W 64
#define HW 4096

#define NCH 4                             // channels per CTA (half group)
#define SROWS 66
#define SCOLS 72                          // interior at col 4 -> 16B-aligned
#define CHT   (SROWS * SCOLS)             // 4752 floats
#define STILE (NCH * CHT)                 // 19008 floats = 76032 B dynamic

// ===========================================================================
// Cluster(2) per (group, sample): CTA h owns channels g*8 + h*4 .. +3.
// Each CTA: full-spatial tile of its 4 channels, own stats, 4-channel
// partial D -> Dbuf; cluster barrier; peer partial via DSMEM; epilogue.
// Grid (2, 64, 16) x 512 threads, 2 CTAs/SM.
// ===========================================================================
__global__ void __launch_bounds__(512, 2) __cluster_dims__(2, 1, 1)
fused_kernel(
    const float* __restrict__ content,
    const float* __restrict__ style,
    const float* __restrict__ dw_w,
    const float* __restrict__ dw_b,
    const float* __restrict__ pk_w,
    const float* __restrict__ pk_b,
    const float* __restrict__ pb_w,
    const float* __restrict__ pb_b,
    float* __restrict__ out)
{
    extern __shared__ float s[];          // [NCH][SROWS][SCOLS] content tile
    __shared__ float Dbuf[4096];          // partial D over own 4 channels
    __shared__ float sd[512];             // style spatial mean
    __shared__ float dredW[16 * 9];       // per-warp d partials
    __shared__ float fd[72];
    __shared__ float fb[NCH], fm[NCH], fr[NCH];
    __shared__ float red[32];
    __shared__ float fS_sh;

    int hf = blockIdx.x;                  // 0/1: which half of the group
    int g  = blockIdx.y;
    int n  = blockIdx.z;
    int tid = threadIdx.x;
    int lane = tid & 31, warp = tid >> 5;
    int c0 = g * 8 + hf * NCH;            // first owned channel
    int cbase = n * 512 + c0;

    // ============ 0. style LDG early (for sd) ==============================
    const float4* sp = (const float4*)(style + (size_t)(n * 512 + tid) * 16);
    float4 a0 = sp[0], a1 = sp[1], a2 = sp[2], a3 = sp[3];

    // ============ 1. content tile load (4 channels), stats in regs =========
    {
        int c       = warp >> 2;          // 0..3 owned channel
        int quarter = warp & 3;           // row residue mod 4
        const float* bc = content + (size_t)(cbase + c) * HW;
        float* sc = s + c * CHT;
        int sub = lane >> 4, q = lane & 15;
        float sum = 0.f, sq = 0.f;
        #pragma unroll
        for (int i = 0; i < 9; i++) {
            int k  = 2 * i + sub;         // 0..17
            int lr = quarter + 4 * k;     // covers 0..65 across warps
            if (lr <= 65) {
                int gr = (lr == 0) ? 1 : (lr == 65 ? 62 : lr - 1);  // reflect
                float4 v = *(const float4*)(bc + gr * W + 4 * q);
                *(float4*)(sc + lr * SCOLS + 4 + 4 * q) = v;
                if (lr >= 1 && lr <= 64) {
                    sum += v.x + v.y + v.z + v.w;
                    sq  += v.x * v.x + v.y * v.y + v.z * v.z + v.w * v.w;
                }
            }
        }
        // halo columns for own 4 channels
        if (tid < NCH * SROWS) {
            int c2 = tid / SROWS, lr = tid % SROWS;
            int gr = (lr == 0) ? 1 : (lr == 65 ? 62 : lr - 1);
            const float* b2 = content + (size_t)(cbase + c2) * HW + gr * W;
            float* row = s + c2 * CHT + lr * SCOLS;
            row[3]  = b2[1];
            row[68] = b2[62];
        }
        #pragma unroll
        for (int off = 16; off; off >>= 1) {
            sum += __shfl_down_sync(0xffffffffu, sum, off);
            sq  += __shfl_down_sync(0xffffffffu, sq,  off);
        }
        if (lane == 0) { red[warp] = sum; red[16 + warp] = sq; }
    }
    // sd
    {
        float tot = a0.x + a0.y + a0.z + a0.w + a1.x + a1.y + a1.z + a1.w
                  + a2.x + a2.y + a2.z + a2.w + a3.x + a3.y + a3.z + a3.w;
        sd[tid] = tot * (1.f / 16.f);
    }
    __syncthreads();

    // ============ 2. prep ==================================================
    // d-dot: thread = (j = tid>>6, chunk = tid&63); style read from L2 global
    {
        int j  = tid >> 6;
        int cc = tid & 63;
        const float4* w4base = (const float4*)dw_w;
        float acc[9];
        #pragma unroll
        for (int i = 0; i < 9; i++) acc[i] = 0.f;

        #pragma unroll
        for (int i = 0; i < 8; i++) {
            int ch = cc + 64 * i;
            float4 w = w4base[j * 512 + ch];
            const float4* stp = (const float4*)(style
                                + (size_t)(n * 512 + ch) * 16);
            float4 s0 = stp[0], s1 = stp[1], s2 = stp[2], s3 = stp[3];
            float stv[16] = { s0.x, s0.y, s0.z, s0.w,  s1.x, s1.y, s1.z, s1.w,
                              s2.x, s2.y, s2.z, s2.w,  s3.x, s3.y, s3.z, s3.w };
            #pragma unroll
            for (int ky = 0; ky < 3; ky++)
                #pragma unroll
                for (int kx = 0; kx < 3; kx++)
                    acc[ky * 3 + kx] += w.x * stv[ky * 4 + kx]
                                      + w.y * stv[ky * 4 + kx + 1]
                                      + w.z * stv[ky * 4 + kx + 4]
                                      + w.w * stv[ky * 4 + kx + 5];
        }
        #pragma unroll
        for (int i = 0; i < 9; i++) {
            #pragma unroll
            for (int off = 16; off; off >>= 1)
                acc[i] += __shfl_xor_sync(0xffffffffu, acc[i], off);
        }
        if (lane == 0) {
            #pragma unroll
            for (int i = 0; i < 9; i++) dredW[warp * 9 + i] = acc[i];
        }
    }
    // bias for own 4 channels (warps 0-3) and S (warp 8)
    if (warp < NCH) {
        const float* row = pb_w + (size_t)(c0 + warp) * 512;
        float acc = 0.f;
        #pragma unroll
        for (int k = 0; k < 16; k++) {
            int c2 = lane + 32 * k;
            acc += row[c2] * sd[c2];
        }
        #pragma unroll
        for (int off = 16; off; off >>= 1)
            acc += __shfl_down_sync(0xffffffffu, acc, off);
        if (lane == 0) fb[warp] = acc + pb_b[c0 + warp];
    } else if (warp == 8) {
        const float4* pkw4 = (const float4*)pk_w;
        const float4* sd4  = (const float4*)sd;
        float4 sv0 = sd4[lane], sv1 = sd4[lane + 32];
        float4 sv2 = sd4[lane + 64], sv3 = sd4[lane + 96];
        float acc = 0.f;
        #pragma unroll
        for (int j = 0; j < 8; j++) {
            float4 w0 = pkw4[j * 128 + lane];
            float4 w1 = pkw4[j * 128 + lane + 32];
            float4 w2 = pkw4[j * 128 + lane + 64];
            float4 w3 = pkw4[j * 128 + lane + 96];
            acc += w0.x * sv0.x + w0.y * sv0.y + w0.z * sv0.z + w0.w * sv0.w
                 + w1.x * sv1.x + w1.y * sv1.y + w1.z * sv1.z + w1.w * sv1.w
                 + w2.x * sv2.x + w2.y * sv2.y + w2.z * sv2.z + w2.w * sv2.w
                 + w3.x * sv3.x + w3.y * sv3.y + w3.z * sv3.z + w3.w * sv3.w;
        }
        #pragma unroll
        for (int off = 16; off; off >>= 1)
            acc += __shfl_down_sync(0xffffffffu, acc, off);
        if (lane == 0) {
            float bsum = 0.f;
            #pragma unroll
            for (int j = 0; j < 8; j++) bsum += pk_b[j];
            fS_sh = acc + bsum;
        }
    }
    __syncthreads();

    // ============ 3. finalize fd + stats ===================================
    if (tid < 72) {
        int j = tid / 9, pos = tid % 9;
        float v = dredW[(2 * j) * 9 + pos] + dredW[(2 * j + 1) * 9 + pos]
                + dw_b[j];
        fd[tid] = v >= 0.f ? v : 0.01f * v;          // leaky
    }
    if (tid >= 96 && tid < 96 + NCH) {
        int o = tid - 96;                 // channel o: warps 4o..4o+3
        float S = red[4 * o] + red[4 * o + 1] + red[4 * o + 2] + red[4 * o + 3];
        float Q = red[16 + 4 * o] + red[16 + 4 * o + 1]
                + red[16 + 4 * o + 2] + red[16 + 4 * o + 3];
        float mean = S * (1.f / HW);
        float var  = (Q - S * S * (1.f / HW)) * (1.f / (HW - 1));  // ddof=1
        fm[o] = mean;
        fr[o] = rsqrtf(var + 1e-5f);
    }
    __syncthreads();

    // ============ 4. conv partial over own 4 channels ======================
    int r2 = tid >> 4;                    // 0..31
    int q4 = (tid & 15) * 4;              // output col base
    int h0 = 2 * r2;                      // output rows h0, h0+1

    float D0[4] = {0.f, 0.f, 0.f, 0.f};
    float D1[4] = {0.f, 0.f, 0.f, 0.f};

    #pragma unroll
    for (int j = 0; j < NCH; j++) {
        const float* sj = s + j * CHT;
        const float* fj = fd + (hf * NCH + j) * 9;     // kernel slot of channel
        #pragma unroll
        for (int rr = 0; rr < 4; rr++) {
            const float* rp = sj + (h0 + rr) * SCOLS + q4;
            float vL = rp[3];
            float4 f4 = *(const float4*)(rp + 4);      // aligned LDS.128
            float vR = rp[8];
            if (rr < 3) {
                float a = fj[rr * 3], b2 = fj[rr * 3 + 1], cc2 = fj[rr * 3 + 2];
                D0[0] += a * vL   + b2 * f4.x + cc2 * f4.y;
                D0[1] += a * f4.x + b2 * f4.y + cc2 * f4.z;
                D0[2] += a * f4.y + b2 * f4.z + cc2 * f4.w;
                D0[3] += a * f4.z + b2 * f4.w + cc2 * vR;
            }
            if (rr >= 1) {
                int kr = rr - 1;
                float a = fj[kr * 3], b2 = fj[kr * 3 + 1], cc2 = fj[kr * 3 + 2];
                D1[0] += a * vL   + b2 * f4.x + cc2 * f4.y;
                D1[1] += a * f4.x + b2 * f4.y + cc2 * f4.z;
                D1[2] += a * f4.y + b2 * f4.z + cc2 * f4.w;
                D1[3] += a * f4.z + b2 * f4.w + cc2 * vR;
            }
        }
    }
    *(float4*)(Dbuf + h0 * 64 + q4)       = make_float4(D0[0], D0[1], D0[2], D0[3]);
    *(float4*)(Dbuf + (h0 + 1) * 64 + q4) = make_float4(D1[0], D1[1], D1[2], D1[3]);
    __syncthreads();

    // ============ 5. cluster exchange of D partials ========================
    asm volatile("barrier.cluster.arrive.aligned;" ::: "memory");
    asm volatile("barrier.cluster.wait.aligned;" ::: "memory");

    {
        uint32_t my = (uint32_t)__cvta_generic_to_shared(Dbuf);
        uint32_t pa;
        uint32_t peer = hf ^ 1;
        asm("mapa.shared::cluster.u32 %0, %1, %2;" : "=r"(pa) : "r"(my), "r"(peer));
        uint32_t o0 = pa + 4u * (h0 * 64 + q4);
        uint32_t o1 = pa + 4u * ((h0 + 1) * 64 + q4);
        float p00, p01, p02, p03, p10, p11, p12, p13;
        asm("ld.shared::cluster.f32 %0, [%1];"      : "=f"(p00) : "r"(o0));
        asm("ld.shared::cluster.f32 %0, [%1+4];"    : "=f"(p01) : "r"(o0));
        asm("ld.shared::cluster.f32 %0, [%1+8];"    : "=f"(p02) : "r"(o0));
        asm("ld.shared::cluster.f32 %0, [%1+12];"   : "=f"(p03) : "r"(o0));
        asm("ld.shared::cluster.f32 %0, [%1];"      : "=f"(p10) : "r"(o1));
        asm("ld.shared::cluster.f32 %0, [%1+4];"    : "=f"(p11) : "r"(o1));
        asm("ld.shared::cluster.f32 %0, [%1+8];"    : "=f"(p12) : "r"(o1));
        asm("ld.shared::cluster.f32 %0, [%1+12];"   : "=f"(p13) : "r"(o1));
        D0[0] += p00; D0[1] += p01; D0[2] += p02; D0[3] += p03;
        D1[0] += p10; D1[1] += p11; D1[2] += p12; D1[3] += p13;
    }

    // ============ 6. epilogue: own 4 output channels =======================
    float S = fS_sh;
    float* obase = out + (size_t)cbase * HW + h0 * W + q4;

    #pragma unroll
    for (int o = 0; o < NCH; o++) {
        const float* so = s + o * CHT;
        float mo = fm[o], ro = fr[o], bo = fb[o];
        float4 r0v, r1v;
        {
            float4 cen = *(const float4*)(so + (h0 + 1) * SCOLS + 4 + q4);
            float p0 = D0[0] * S + bo, p1 = D0[1] * S + bo;
            float p2 = D0[2] * S + bo, p3 = D0[3] * S + bo;
            p0 = p0 >= 0.f ? p0 : 0.01f * p0;
            p1 = p1 >= 0.f ? p1 : 0.01f * p1;
            p2 = p2 >= 0.f ? p2 : 0.01f * p2;
            p3 = p3 >= 0.f ? p3 : 0.01f * p3;
            r0v.x = (cen.x - mo) * ro * p0;
            r0v.y = (cen.y - mo) * ro * p1;
            r0v.z = (cen.z - mo) * ro * p2;
            r0v.w = (cen.w - mo) * ro * p3;
        }
        {
            float4 cen = *(const float4*)(so + (h0 + 2) * SCOLS + 4 + q4);
            float p0 = D1[0] * S + bo, p1 = D1[1] * S + bo;
            float p2 = D1[2] * S + bo, p3 = D1[3] * S + bo;
            p0 = p0 >= 0.f ? p0 : 0.01f * p0;
            p1 = p1 >= 0.f ? p1 : 0.01f * p1;
            p2 = p2 >= 0.f ? p2 : 0.01f * p2;
            p3 = p3 >= 0.f ? p3 : 0.01f * p3;
            r1v.x = (cen.x - mo) * ro * p0;
            r1v.y = (cen.y - mo) * ro * p1;
            r1v.z = (cen.z - mo) * ro * p2;
            r1v.w = (cen.w - mo) * ro * p3;
        }
        __stcs((float4*)(obase + (size_t)o * HW),     r0v);
        __stcs((float4*)(obase + (size_t)o * HW + W), r1v);
    }

    // no CTA may exit while its Dbuf can still be read by the peer
    asm volatile("barrier.cluster.arrive.aligned;" ::: "memory");
    asm volatile("barrier.cluster.wait.aligned;" ::: "memory");
}

// ===========================================================================
extern "C" void kernel_launch(void* const* d_in, const int* in_sizes, int n_in,
                              void* d_out, int out_size)
{
    const float* style   = (const float*)d_in[0];
    const float* content = (const float*)d_in[1];
    const float* dw_w    = (const float*)d_in[2];
    const float* dw_b    = (const float*)d_in[3];
    const float* pk_w    = (const float*)d_in[4];
    const float* pk_b    = (const float*)d_in[5];
    const float* pb_w    = (const float*)d_in[6];
    const float* pb_b    = (const float*)d_in[7];
    float* out = (float*)d_out;

    static bool attr_set = false;
    if (!attr_set) {
        cudaFuncSetAttribute(fused_kernel,
                             cudaFuncAttributeMaxDynamicSharedMemorySize,
                             STILE * sizeof(float));
        attr_set = true;
    }

    fused_kernel<<<dim3(2, NG, N_SAMP), 512, STILE * sizeof(float)>>>(
        content, style, dw_w, dw_b, pk_w, pk_b, pb_w, pb_b, out);
}

// round 16
// speedup vs baseline: 1.4105x; 1.4105x over previous
#include <cuda_runtime.h>
#include <cstdint>
#include <math.h>

#define CH 512
#define NG 64
#define N_SAMP 16
#define H 64
#define W 64
#define HW 4096

#define SROWS 66
#define SCOLS 72                          // interior at col 4 -> 16B-aligned
#define CHT   (SROWS * SCOLS)             // 4752 floats
#define STILE (8 * CHT)                   // 38016 floats = 152064 B dynamic

// ===========================================================================
// ONE fused kernel. Grid (64, 16) x 1024 threads, 1 CTA/SM, 32 warps (occ 50%).
//  1. load: 4 warps per channel (R15 row scheme), stats in regs
//  2. prep: d-dot 4 channels/thread over 1024 threads; bias/S dots
//  3. finalize fd / stats
//  4. conv: two 512-thread halves, 4 channels each -> partial D in smem
//  5. sum partials; epilogue split by channel halves
// ===========================================================================
__global__ void __launch_bounds__(1024, 1) fused_kernel(
    const float* __restrict__ content,
    const float* __restrict__ style,
    const float* __restrict__ dw_w,
    const float* __restrict__ dw_b,
    const float* __restrict__ pk_w,
    const float* __restrict__ pk_b,
    const float* __restrict__ pb_w,
    const float* __restrict__ pb_b,
    float* __restrict__ out)
{
    extern __shared__ float s[];          // [8][SROWS][SCOLS] content tile
    __shared__ float st[16 * 512];        // style TRANSPOSED [pos][channel]
    __shared__ float Dbuf[2][4096];       // partial D per half (32 KB)
    __shared__ float sd[512];             // style spatial mean
    __shared__ float dredW[32 * 9];       // per-warp d partials
    __shared__ float fd[72];
    __shared__ float fb[8], fm[8], fr[8];
    __shared__ float red[64];
    __shared__ float fS_sh;

    int g = blockIdx.x;
    int n = blockIdx.y;
    int tid = threadIdx.x;
    int lane = tid & 31, warp = tid >> 5;
    int cbase = n * 512 + g * 8;

    // ============ 0. style LDG early (tid < 512: one channel each) =========
    float4 a0, a1, a2, a3;
    if (tid < 512) {
        const float4* sp = (const float4*)(style + (size_t)(n * 512 + tid) * 16);
        a0 = sp[0]; a1 = sp[1]; a2 = sp[2]; a3 = sp[3];
    }

    // ============ 1. content tile load, stats in regs ======================
    {
        int c       = warp >> 2;          // channel 0..7
        int quarter = warp & 3;           // row residue mod 4
        const float* bc = content + (size_t)(cbase + c) * HW;
        float* sc = s + c * CHT;
        int sub = lane >> 4, q = lane & 15;
        float sum = 0.f, sq = 0.f;
        #pragma unroll
        for (int i = 0; i < 9; i++) {
            int k  = 2 * i + sub;         // 0..17
            int lr = quarter + 4 * k;     // covers 0..65 across quarters
            if (lr <= 65) {
                int gr = (lr == 0) ? 1 : (lr == 65 ? 62 : lr - 1);  // reflect
                float4 v = *(const float4*)(bc + gr * W + 4 * q);
                *(float4*)(sc + lr * SCOLS + 4 + 4 * q) = v;
                if (lr >= 1 && lr <= 64) {
                    sum += v.x + v.y + v.z + v.w;
                    sq  += v.x * v.x + v.y * v.y + v.z * v.z + v.w * v.w;
                }
            }
        }
        // halo columns
        if (tid < 8 * SROWS) {
            int c2 = tid / SROWS, lr = tid % SROWS;
            int gr = (lr == 0) ? 1 : (lr == 65 ? 62 : lr - 1);
            const float* b2 = content + (size_t)(cbase + c2) * HW + gr * W;
            float* row = s + c2 * CHT + lr * SCOLS;
            row[3]  = b2[1];
            row[68] = b2[62];
        }
        #pragma unroll
        for (int off = 16; off; off >>= 1) {
            sum += __shfl_down_sync(0xffffffffu, sum, off);
            sq  += __shfl_down_sync(0xffffffffu, sq,  off);
        }
        if (lane == 0) { red[warp] = sum; red[32 + warp] = sq; }
    }
    // style -> transposed smem + sd (tid < 512)
    if (tid < 512) {
        st[ 0 * 512 + tid] = a0.x;  st[ 1 * 512 + tid] = a0.y;
        st[ 2 * 512 + tid] = a0.z;  st[ 3 * 512 + tid] = a0.w;
        st[ 4 * 512 + tid] = a1.x;  st[ 5 * 512 + tid] = a1.y;
        st[ 6 * 512 + tid] = a1.z;  st[ 7 * 512 + tid] = a1.w;
        st[ 8 * 512 + tid] = a2.x;  st[ 9 * 512 + tid] = a2.y;
        st[10 * 512 + tid] = a2.z;  st[11 * 512 + tid] = a2.w;
        st[12 * 512 + tid] = a3.x;  st[13 * 512 + tid] = a3.y;
        st[14 * 512 + tid] = a3.z;  st[15 * 512 + tid] = a3.w;
        float tot = a0.x + a0.y + a0.z + a0.w + a1.x + a1.y + a1.z + a1.w
                  + a2.x + a2.y + a2.z + a2.w + a3.x + a3.y + a3.z + a3.w;
        sd[tid] = tot * (1.f / 16.f);
    }
    __syncthreads();

    // ============ 2. prep ==================================================
    // d-dot: thread = (j = tid>>7, chunk = tid&127); 4 channels per thread
    {
        int j  = tid >> 7;
        int cc = tid & 127;
        const float4* w4base = (const float4*)dw_w;
        float acc[9];
        #pragma unroll
        for (int i = 0; i < 9; i++) acc[i] = 0.f;

        #pragma unroll
        for (int i = 0; i < 4; i++) {
            int ch = cc + 128 * i;
            float4 w = w4base[j * 512 + ch];
            float stv[16];
            #pragma unroll
            for (int p = 0; p < 16; p++) stv[p] = st[p * 512 + ch];
            #pragma unroll
            for (int ky = 0; ky < 3; ky++)
                #pragma unroll
                for (int kx = 0; kx < 3; kx++)
                    acc[ky * 3 + kx] += w.x * stv[ky * 4 + kx]
                                      + w.y * stv[ky * 4 + kx + 1]
                                      + w.z * stv[ky * 4 + kx + 4]
                                      + w.w * stv[ky * 4 + kx + 5];
        }
        #pragma unroll
        for (int i = 0; i < 9; i++) {
            #pragma unroll
            for (int off = 16; off; off >>= 1)
                acc[i] += __shfl_xor_sync(0xffffffffu, acc[i], off);
        }
        if (lane == 0) {
            #pragma unroll
            for (int i = 0; i < 9; i++) dredW[warp * 9 + i] = acc[i];
        }
    }
    // bias (warps 0-7) and S (warp 8)
    if (warp < 8) {
        const float* row = pb_w + (size_t)(g * 8 + warp) * 512;
        float acc = 0.f;
        #pragma unroll
        for (int k = 0; k < 16; k++) {
            int c2 = lane + 32 * k;
            acc += row[c2] * sd[c2];
        }
        #pragma unroll
        for (int off = 16; off; off >>= 1)
            acc += __shfl_down_sync(0xffffffffu, acc, off);
        if (lane == 0) fb[warp] = acc + pb_b[g * 8 + warp];
    } else if (warp == 8) {
        const float4* pkw4 = (const float4*)pk_w;
        const float4* sd4  = (const float4*)sd;
        float4 sv0 = sd4[lane], sv1 = sd4[lane + 32];
        float4 sv2 = sd4[lane + 64], sv3 = sd4[lane + 96];
        float acc = 0.f;
        #pragma unroll
        for (int j = 0; j < 8; j++) {
            float4 w0 = pkw4[j * 128 + lane];
            float4 w1 = pkw4[j * 128 + lane + 32];
            float4 w2 = pkw4[j * 128 + lane + 64];
            float4 w3 = pkw4[j * 128 + lane + 96];
            acc += w0.x * sv0.x + w0.y * sv0.y + w0.z * sv0.z + w0.w * sv0.w
                 + w1.x * sv1.x + w1.y * sv1.y + w1.z * sv1.z + w1.w * sv1.w
                 + w2.x * sv2.x + w2.y * sv2.y + w2.z * sv2.z + w2.w * sv2.w
                 + w3.x * sv3.x + w3.y * sv3.y + w3.z * sv3.z + w3.w * sv3.w;
        }
        #pragma unroll
        for (int off = 16; off; off >>= 1)
            acc += __shfl_down_sync(0xffffffffu, acc, off);
        if (lane == 0) {
            float bsum = 0.f;
            #pragma unroll
            for (int j = 0; j < 8; j++) bsum += pk_b[j];
            fS_sh = acc + bsum;
        }
    }
    __syncthreads();

    // ============ 3. finalize ==============================================
    if (tid < 72) {
        int j = tid / 9, pos = tid % 9;
        float v = dredW[(4 * j) * 9 + pos] + dredW[(4 * j + 1) * 9 + pos]
                + dredW[(4 * j + 2) * 9 + pos] + dredW[(4 * j + 3) * 9 + pos]
                + dw_b[j];
        fd[tid] = v >= 0.f ? v : 0.01f * v;          // leaky
    }
    if (tid >= 96 && tid < 104) {
        int o = tid - 96;                 // channel o: warps 4o..4o+3
        float S = red[4 * o] + red[4 * o + 1] + red[4 * o + 2] + red[4 * o + 3];
        float Q = red[32 + 4 * o] + red[32 + 4 * o + 1]
                + red[32 + 4 * o + 2] + red[32 + 4 * o + 3];
        float mean = S * (1.f / HW);
        float var  = (Q - S * S * (1.f / HW)) * (1.f / (HW - 1));  // ddof=1
        fm[o] = mean;
        fr[o] = rsqrtf(var + 1e-5f);
    }
    __syncthreads();

    // ============ 4. conv: two halves x 4 channels, 2 rows x 4 cols ========
    int half = tid >> 9;                  // 0/1: channel half
    int t    = tid & 511;
    int r2 = t >> 4;                      // 0..31
    int q4 = (t & 15) * 4;                // output col base
    int h0 = 2 * r2;                      // output rows h0, h0+1

    float D0[4] = {0.f, 0.f, 0.f, 0.f};
    float D1[4] = {0.f, 0.f, 0.f, 0.f};

    #pragma unroll
    for (int jj = 0; jj < 4; jj++) {
        int j = half * 4 + jj;
        const float* sj = s + j * CHT;
        const float* fj = fd + j * 9;
        #pragma unroll
        for (int rr = 0; rr < 4; rr++) {
            const float* rp = sj + (h0 + rr) * SCOLS + q4;
            float vL = rp[3];
            float4 f4 = *(const float4*)(rp + 4);   // aligned LDS.128
            float vR = rp[8];
            if (rr < 3) {
                float a = fj[rr * 3], b2 = fj[rr * 3 + 1], cc2 = fj[rr * 3 + 2];
                D0[0] += a * vL   + b2 * f4.x + cc2 * f4.y;
                D0[1] += a * f4.x + b2 * f4.y + cc2 * f4.z;
                D0[2] += a * f4.y + b2 * f4.z + cc2 * f4.w;
                D0[3] += a * f4.z + b2 * f4.w + cc2 * vR;
            }
            if (rr >= 1) {
                int kr = rr - 1;
                float a = fj[kr * 3], b2 = fj[kr * 3 + 1], cc2 = fj[kr * 3 + 2];
                D1[0] += a * vL   + b2 * f4.x + cc2 * f4.y;
                D1[1] += a * f4.x + b2 * f4.y + cc2 * f4.z;
                D1[2] += a * f4.y + b2 * f4.z + cc2 * f4.w;
                D1[3] += a * f4.z + b2 * f4.w + cc2 * vR;
            }
        }
    }
    *(float4*)(&Dbuf[half][h0 * 64 + q4])       = make_float4(D0[0], D0[1], D0[2], D0[3]);
    *(float4*)(&Dbuf[half][(h0 + 1) * 64 + q4]) = make_float4(D1[0], D1[1], D1[2], D1[3]);
    __syncthreads();

    // ============ 5. sum partials + epilogue (own channel half) ============
    {
        float4 p0 = *(const float4*)(&Dbuf[half ^ 1][h0 * 64 + q4]);
        float4 p1 = *(const float4*)(&Dbuf[half ^ 1][(h0 + 1) * 64 + q4]);
        D0[0] += p0.x; D0[1] += p0.y; D0[2] += p0.z; D0[3] += p0.w;
        D1[0] += p1.x; D1[1] += p1.y; D1[2] += p1.z; D1[3] += p1.w;
    }

    float S = fS_sh;

    #pragma unroll
    for (int oo = 0; oo < 4; oo++) {
        int o = half * 4 + oo;
        const float* so = s + o * CHT;
        float mo = fm[o], ro = fr[o], bo = fb[o];
        float* op = out + (size_t)(cbase + o) * HW + h0 * W + q4;
        float4 r0v, r1v;
        {
            float4 cen = *(const float4*)(so + (h0 + 1) * SCOLS + 4 + q4);
            float p0 = D0[0] * S + bo, p1 = D0[1] * S + bo;
            float p2 = D0[2] * S + bo, p3 = D0[3] * S + bo;
            p0 = p0 >= 0.f ? p0 : 0.01f * p0;
            p1 = p1 >= 0.f ? p1 : 0.01f * p1;
            p2 = p2 >= 0.f ? p2 : 0.01f * p2;
            p3 = p3 >= 0.f ? p3 : 0.01f * p3;
            r0v.x = (cen.x - mo) * ro * p0;
            r0v.y = (cen.y - mo) * ro * p1;
            r0v.z = (cen.z - mo) * ro * p2;
            r0v.w = (cen.w - mo) * ro * p3;
        }
        {
            float4 cen = *(const float4*)(so + (h0 + 2) * SCOLS + 4 + q4);
            float p0 = D1[0] * S + bo, p1 = D1[1] * S + bo;
            float p2 = D1[2] * S + bo, p3 = D1[3] * S + bo;
            p0 = p0 >= 0.f ? p0 : 0.01f * p0;
            p1 = p1 >= 0.f ? p1 : 0.01f * p1;
            p2 = p2 >= 0.f ? p2 : 0.01f * p2;
            p3 = p3 >= 0.f ? p3 : 0.01f * p3;
            r1v.x = (cen.x - mo) * ro * p0;
            r1v.y = (cen.y - mo) * ro * p1;
            r1v.z = (cen.z - mo) * ro * p2;
            r1v.w = (cen.w - mo) * ro * p3;
        }
        __stcs((float4*)op,       r0v);
        __stcs((float4*)(op + W), r1v);
    }
}

// ===========================================================================
extern "C" void kernel_launch(void* const* d_in, const int* in_sizes, int n_in,
                              void* d_out, int out_size)
{
    const float* style   = (const float*)d_in[0];
    const float* content = (const float*)d_in[1];
    const float* dw_w    = (const float*)d_in[2];
    const float* dw_b    = (const float*)d_in[3];
    const float* pk_w    = (const float*)d_in[4];
    const float* pk_b    = (const float*)d_in[5];
    const float* pb_w    = (const float*)d_in[6];
    const float* pb_b    = (const float*)d_in[7];
    float* out = (float*)d_out;

    static bool attr_set = false;
    if (!attr_set) {
        cudaFuncSetAttribute(fused_kernel,
                             cudaFuncAttributeMaxDynamicSharedMemorySize,
                             STILE * sizeof(float));
        attr_set = true;
    }

    fused_kernel<<<dim3(NG, N_SAMP), 1024, STILE * sizeof(float)>>>(
        content, style, dw_w, dw_b, pk_w, pk_b, pb_w, pb_b, out);
}